// round 7
// baseline (speedup 1.0000x reference)
#include <cuda_runtime.h>
#include <math.h>

#define B_ 8
#define NPTS 2048
#define KNB 10
#define KSEL 16
#define EPSV 1e-5f
#define MTOT (B_ * NPTS)

// ---------------- scratch (no allocation allowed) ----------------
__device__ float  d_x1[MTOT * 64];
__device__ float  d_x2[MTOT * 64];
__device__ float  d_x3[MTOT * 128];
__device__ float  d_x4[MTOT * 256];
__device__ float  d_yz[MTOT * 512];
__device__ int    d_idxbuf[MTOT * KNB];
__device__ int    d_cand[MTOT * KSEL];
__device__ double d_norm[MTOT];
__device__ float  d_wp[512 * 128];
__device__ float  d_part[B_ * 16 * 512];
__device__ float  d_gmax[B_ * 512];

// ---------------- helpers ----------------
template <int K>
__device__ __forceinline__ void insertK(float tv[K], int ti[K], float d, int m) {
    if (d <= tv[K - 1]) return;
    float cv = d; int ci = m;
#pragma unroll
    for (int p = 0; p < K; ++p) {
        if (cv > tv[p]) {
            float t = tv[p]; tv[p] = cv; cv = t;
            int u = ti[p]; ti[p] = ci; ci = u;
        }
    }
}

// ---------------- fp64 point norms: one warp per point ----------------
template <int C>
__global__ void compute_norms(const float* __restrict__ x, double* __restrict__ nrm) {
    const unsigned FULL = 0xffffffffu;
    const int gw = (blockIdx.x * 256 + threadIdx.x) >> 5;
    const int lane = threadIdx.x & 31;
    if (gw >= MTOT) return;
    const float* p = x + (size_t)gw * C;
    double s = 0.0;
#pragma unroll
    for (int c = lane; c < C; c += 32) { double v = (double)p[c]; s += v * v; }
#pragma unroll
    for (int off = 16; off; off >>= 1) s += __shfl_down_sync(FULL, s, off);
    if (lane == 0) nrm[gw] = s;
}

// ---------------- kNN pass 1 (fp32): lane = center (regs), candidates broadcast ----------------
// Block = 64 threads = 64 centers. Tile = 64 candidates staged in shared.
// Each lane maintains its own exact top-KSEL over all 2048 candidates.
template <int C>
__global__ void __launch_bounds__(64)
knn_kernel(const float* __restrict__ x, int* __restrict__ candout) {
    const unsigned FULL = 0xffffffffu;
    constexpr int TC = 64;  // candidates per tile
    const int b = blockIdx.y;
    const int n0 = blockIdx.x * TC;
    const int tid = threadIdx.x;          // 0..63
    const int lane = tid & 31;

    __shared__ float s_tile[TC][C];
    __shared__ float s_nm[TC];

    const float* xb = x + (size_t)b * NPTS * C;
    const int n = n0 + tid;

    // center into registers
    float creg[C];
    if (C % 4 == 0) {
#pragma unroll
        for (int c = 0; c < C; c += 4) {
            float4 t = *(const float4*)&xb[(size_t)n * C + c];
            creg[c] = t.x; creg[c + 1] = t.y; creg[c + 2] = t.z; creg[c + 3] = t.w;
        }
    } else {
#pragma unroll
        for (int c = 0; c < C; ++c) creg[c] = xb[(size_t)n * C + c];
    }
    float cn = 0.f;
#pragma unroll
    for (int c = 0; c < C; ++c) cn += creg[c] * creg[c];

    float tv[KSEL]; int ti[KSEL];
#pragma unroll
    for (int q = 0; q < KSEL; ++q) { tv[q] = -INFINITY; ti[q] = 0x7fffffff; }

    for (int m0 = 0; m0 < NPTS; m0 += TC) {
        __syncthreads();
        if (C % 4 == 0) {
            constexpr int C4 = C / 4;
            // fused tile load + per-row norm via aligned subgroup shuffle reduce
#pragma unroll
            for (int i = tid; i < TC * C4; i += 64) {
                int r = i / C4, c4 = i % C4;
                float4 t = ((const float4*)&xb[(size_t)(m0 + r) * C])[c4];
                ((float4*)&s_tile[r][0])[c4] = t;
                float pn = t.x * t.x + t.y * t.y + t.z * t.z + t.w * t.w;
#pragma unroll
                for (int off = (C4 < 32 ? C4 : 32) / 2; off; off >>= 1)
                    pn += __shfl_down_sync(FULL, pn, off, (C4 < 32 ? C4 : 32));
                if ((lane & ((C4 < 32 ? C4 : 32) - 1)) == 0) s_nm[r] = pn;
            }
        } else {
            for (int i = tid; i < TC * C; i += 64)
                s_tile[i / C][i % C] = xb[(size_t)(m0 + i / C) * C + i % C];
            __syncthreads();
            if (tid < TC) {
                float s = 0.f;
#pragma unroll
                for (int c = 0; c < C; ++c) s += s_tile[tid][c] * s_tile[tid][c];
                s_nm[tid] = s;
            }
        }
        __syncthreads();

#pragma unroll 2
        for (int j = 0; j < TC; ++j) {
            float d;
            if (C % 4 == 0) {
                float a0 = 0.f, a1 = 0.f, a2 = 0.f, a3 = 0.f;
#pragma unroll
                for (int c = 0; c < C; c += 4) {
                    float4 t = *(const float4*)&s_tile[j][c];  // broadcast
                    a0 += creg[c + 0] * t.x;
                    a1 += creg[c + 1] * t.y;
                    a2 += creg[c + 2] * t.z;
                    a3 += creg[c + 3] * t.w;
                }
                d = 2.f * ((a0 + a1) + (a2 + a3)) - cn - s_nm[j];
            } else {
                float acc = 0.f;
#pragma unroll
                for (int c = 0; c < C; ++c) acc += creg[c] * s_tile[j][c];
                d = 2.f * acc - cn - s_nm[j];
            }
            insertK<KSEL>(tv, ti, d, m0 + j);
        }
    }

    int* out = candout + (size_t)(b * NPTS + n) * KSEL;
#pragma unroll
    for (int q = 0; q < KSEL; ++q) out[q] = ti[q];
}

// ---------------- kNN pass 2: fp64 exact rescore of top-16, keep true top-10 ----------------
template <int C>
__global__ void rerank(const float* __restrict__ x, const double* __restrict__ nrm,
                       const int* __restrict__ cand, int* __restrict__ idxout) {
    const unsigned FULL = 0xffffffffu;
    __shared__ float s_cent[8][C];
    const int warp = threadIdx.x >> 5, lane = threadIdx.x & 31;
    const int point = blockIdx.x * 8 + warp;          // global b*NPTS+n
    const int browbase = point & ~(NPTS - 1);
    const float* xb = x + (size_t)browbase * C;
    const int nloc = point - browbase;

    for (int c = lane; c < C; c += 32) s_cent[warp][c] = xb[(size_t)nloc * C + c];
    __syncwarp();

    double d = -INFINITY;
    int mi = 0x7fffffff;
    if (lane < KSEL) {
        mi = cand[(size_t)point * KSEL + lane];
        const float* row = xb + (size_t)mi * C;
        if (C % 4 == 0) {
            double a0 = 0.0, a1 = 0.0, a2 = 0.0, a3 = 0.0;
#pragma unroll
            for (int c = 0; c < C; c += 4) {
                float4 r = *(const float4*)&row[c];
                a0 += (double)s_cent[warp][c + 0] * (double)r.x;
                a1 += (double)s_cent[warp][c + 1] * (double)r.y;
                a2 += (double)s_cent[warp][c + 2] * (double)r.z;
                a3 += (double)s_cent[warp][c + 3] * (double)r.w;
            }
            d = 2.0 * ((a0 + a1) + (a2 + a3)) - nrm[point] - nrm[browbase + mi];
        } else {
            double dot = 0.0;
#pragma unroll
            for (int c = 0; c < C; ++c)
                dot += (double)s_cent[warp][c] * (double)row[c];
            d = 2.0 * dot - nrm[point] - nrm[browbase + mi];
        }
    }

    int* out = idxout + (size_t)point * KNB;
#pragma unroll
    for (int r = 0; r < KNB; ++r) {
        double v = d; int i_ = mi;
#pragma unroll
        for (int off = 16; off; off >>= 1) {
            double ov = __shfl_down_sync(FULL, v, off);
            int    oi = __shfl_down_sync(FULL, i_, off);
            if (ov > v || (ov == v && oi < i_)) { v = ov; i_ = oi; }
        }
        double bv = __shfl_sync(FULL, v, 0);
        int    bi = __shfl_sync(FULL, i_, 0);
        if (lane == 0) out[r] = bi;
        if (d == bv && mi == bi) d = -INFINITY;
    }
}

// ---------------- weight prep: Wp = [A ; B - A] ----------------
__global__ void prep_w(const float* __restrict__ w, float* __restrict__ wp, int O, int C) {
    int i = blockIdx.x * 256 + threadIdx.x;
    if (i < O * C) {
        int o = i / C, c = i % C;
        float a = w[(size_t)o * 2 * C + c];
        wp[i] = a;
        wp[(size_t)O * C + i] = w[(size_t)o * 2 * C + C + c] - a;
    }
}

// ---------------- GEMM: Y[M,N] = X[M,K] * W[N,K]^T, 64x64 tiles, fp32 ----------------
__global__ void gemm64(const float* __restrict__ X, const float* __restrict__ W,
                       float* __restrict__ Y, int M, int K, int N) {
    __shared__ float sA[16][64];
    __shared__ float sB[16][64];
    const int tid = threadIdx.x;
    const int tx = tid & 15, ty = tid >> 4;
    const int m0 = blockIdx.y * 64, n0 = blockIdx.x * 64;
    float acc[4][4] = {};
    for (int kt = 0; kt < K; kt += 16) {
        for (int i = tid; i < 64 * 16; i += 256) {
            int r = i >> 4, kk = i & 15;
            int kg = kt + kk;
            sA[kk][r] = (kg < K) ? X[(size_t)(m0 + r) * K + kg] : 0.f;
            sB[kk][r] = (kg < K) ? W[(size_t)(n0 + r) * K + kg] : 0.f;
        }
        __syncthreads();
#pragma unroll
        for (int kk = 0; kk < 16; ++kk) {
            float4 a  = *(const float4*)&sA[kk][ty * 4];
            float4 bq = *(const float4*)&sB[kk][tx * 4];
            float av[4] = {a.x, a.y, a.z, a.w};
            float bv[4] = {bq.x, bq.y, bq.z, bq.w};
#pragma unroll
            for (int i2 = 0; i2 < 4; ++i2)
#pragma unroll
                for (int j2 = 0; j2 < 4; ++j2)
                    acc[i2][j2] += av[i2] * bv[j2];
        }
        __syncthreads();
    }
#pragma unroll
    for (int i2 = 0; i2 < 4; ++i2)
#pragma unroll
        for (int j2 = 0; j2 < 4; ++j2)
            Y[(size_t)(m0 + ty * 4 + i2) * N + n0 + tx * 4 + j2] = acc[i2][j2];
}

// ---------------- gather + reduce + BN + lrelu ----------------
__global__ void edge_reduce(const float* __restrict__ yz, const int* __restrict__ idx,
                            const float* __restrict__ gg, const float* __restrict__ bb,
                            const float* __restrict__ rm, const float* __restrict__ rv,
                            float* __restrict__ xout, float* __restrict__ outT, int O) {
    const int bn = blockIdx.x;
    const int b = bn >> 11, n = bn & 2047;
    const int o = threadIdx.x;
    __shared__ int sj[KNB];
    if (o < KNB) sj[o] = idx[(size_t)bn * KNB + o];
    __syncthreads();
    const double scale = (double)gg[o] / sqrt((double)rv[o] + 1e-5);
    const int twoO = 2 * O;
    const float z = yz[(size_t)bn * twoO + O + o];
    const int browbase = b << 11;
    float red;
    if (scale >= 0.0) {
        red = -INFINITY;
#pragma unroll
        for (int j = 0; j < KNB; ++j)
            red = fmaxf(red, yz[(size_t)(browbase + sj[j]) * twoO + o]);
    } else {
        red = INFINITY;
#pragma unroll
        for (int j = 0; j < KNB; ++j)
            red = fminf(red, yz[(size_t)(browbase + sj[j]) * twoO + o]);
    }
    double h = (((double)red + (double)z) - (double)rm[o]) * scale + (double)bb[o];
    float hf = (float)h;
    float r = hf >= 0.f ? hf : 0.2f * hf;
    xout[(size_t)bn * O + o] = r;
    if (outT) outT[((size_t)b * O + o) * NPTS + n] = r;
}

// ---------------- global max (two pass) ----------------
__global__ void gmax_partial(const float* __restrict__ x1, const float* __restrict__ x2,
                             const float* __restrict__ x3, const float* __restrict__ x4,
                             float* __restrict__ part) {
    const int b = blockIdx.x, chunk = blockIdx.y;
    const int c = threadIdx.x;  // 0..511
    const float* src; int O, off;
    if (c < 64)       { src = x1; O = 64;  off = c; }
    else if (c < 128) { src = x2; O = 64;  off = c - 64; }
    else if (c < 256) { src = x3; O = 128; off = c - 128; }
    else              { src = x4; O = 256; off = c - 256; }
    float m = -INFINITY;
    const int nbeg = chunk * 128;
    const float* p = src + ((size_t)b * NPTS + nbeg) * O + off;
    for (int n = 0; n < 128; ++n) m = fmaxf(m, p[(size_t)n * O]);
    part[((size_t)b * 16 + chunk) * 512 + c] = m;
}

__global__ void gmax_final(const float* __restrict__ part, float* __restrict__ gmax) {
    const int b = blockIdx.x, c = threadIdx.x;
    float m = -INFINITY;
    for (int ch = 0; ch < 16; ++ch)
        m = fmaxf(m, part[((size_t)b * 16 + ch) * 512 + c]);
    gmax[(size_t)b * 512 + c] = m;
}

// ---------------- final FC + BN + lrelu (fp64 accumulate) ----------------
__global__ void final_fc(const float* __restrict__ gmax, const float* __restrict__ lw,
                         const float* __restrict__ lb, const float* __restrict__ g5,
                         const float* __restrict__ b5, const float* __restrict__ rm5,
                         const float* __restrict__ rv5, float* __restrict__ out) {
    const int b = blockIdx.y;
    const int o = blockIdx.x * 256 + threadIdx.x;
    __shared__ float sg[512];
    for (int i = threadIdx.x; i < 512; i += 256) sg[i] = gmax[(size_t)b * 512 + i];
    __syncthreads();
    const float* wrow = lw + (size_t)o * 512;
    double acc = 0.0;
#pragma unroll 8
    for (int c = 0; c < 512; ++c) acc += (double)sg[c] * (double)wrow[c];
    acc += (double)lb[o];
    const double scale = (double)g5[o] / sqrt((double)rv5[o] + 1e-5);
    double h = (acc - (double)rm5[o]) * scale + (double)b5[o];
    float hf = (float)h;
    out[(size_t)b * 1024 + o] = hf >= 0.f ? hf : 0.2f * hf;
}

// ---------------- launch ----------------
extern "C" void kernel_launch(void* const* d_in, const int* in_sizes, int n_in,
                              void* d_out, int out_size) {
    const float* x    = (const float*)d_in[0];
    const float* w1   = (const float*)d_in[1];
    const float* g1   = (const float*)d_in[2];
    const float* b1   = (const float*)d_in[3];
    const float* rm1  = (const float*)d_in[4];
    const float* rv1  = (const float*)d_in[5];
    const float* w2   = (const float*)d_in[6];
    const float* g2   = (const float*)d_in[7];
    const float* b2   = (const float*)d_in[8];
    const float* rm2  = (const float*)d_in[9];
    const float* rv2  = (const float*)d_in[10];
    const float* w3   = (const float*)d_in[11];
    const float* g3   = (const float*)d_in[12];
    const float* b3   = (const float*)d_in[13];
    const float* rm3  = (const float*)d_in[14];
    const float* rv3  = (const float*)d_in[15];
    const float* w4   = (const float*)d_in[16];
    const float* g4   = (const float*)d_in[17];
    const float* b4   = (const float*)d_in[18];
    const float* rm4  = (const float*)d_in[19];
    const float* rv4  = (const float*)d_in[20];
    const float* lw   = (const float*)d_in[21];
    const float* lb   = (const float*)d_in[22];
    const float* g5   = (const float*)d_in[23];
    const float* b5   = (const float*)d_in[24];
    const float* rm5  = (const float*)d_in[25];
    const float* rv5  = (const float*)d_in[26];

    float *x1, *x2, *x3, *x4, *yz, *wp, *part, *gmax;
    int *idx, *cand;
    double* nrm;
    cudaGetSymbolAddress((void**)&x1, d_x1);
    cudaGetSymbolAddress((void**)&x2, d_x2);
    cudaGetSymbolAddress((void**)&x3, d_x3);
    cudaGetSymbolAddress((void**)&x4, d_x4);
    cudaGetSymbolAddress((void**)&yz, d_yz);
    cudaGetSymbolAddress((void**)&idx, d_idxbuf);
    cudaGetSymbolAddress((void**)&cand, d_cand);
    cudaGetSymbolAddress((void**)&nrm, d_norm);
    cudaGetSymbolAddress((void**)&wp, d_wp);
    cudaGetSymbolAddress((void**)&part, d_part);
    cudaGetSymbolAddress((void**)&gmax, d_gmax);

    float* out = (float*)d_out;
    float* x4T = out + B_ * 1024;

    const dim3 knn_grid(NPTS / 64, B_);
    const int nrm_blocks = (MTOT * 32 + 255) / 256;
    const int rr_blocks = MTOT / 8;

    // layer 1: C=5 -> O=64
    compute_norms<5><<<nrm_blocks, 256>>>(x, nrm);
    knn_kernel<5><<<knn_grid, 64>>>(x, cand);
    rerank<5><<<rr_blocks, 256>>>(x, nrm, cand, idx);
    prep_w<<<(64 * 5 + 255) / 256, 256>>>(w1, wp, 64, 5);
    gemm64<<<dim3(128 / 64, MTOT / 64), 256>>>(x, wp, yz, MTOT, 5, 128);
    edge_reduce<<<MTOT, 64>>>(yz, idx, g1, b1, rm1, rv1, x1, nullptr, 64);

    // layer 2: C=64 -> O=64
    compute_norms<64><<<nrm_blocks, 256>>>(x1, nrm);
    knn_kernel<64><<<knn_grid, 64>>>(x1, cand);
    rerank<64><<<rr_blocks, 256>>>(x1, nrm, cand, idx);
    prep_w<<<(64 * 64 + 255) / 256, 256>>>(w2, wp, 64, 64);
    gemm64<<<dim3(128 / 64, MTOT / 64), 256>>>(x1, wp, yz, MTOT, 64, 128);
    edge_reduce<<<MTOT, 64>>>(yz, idx, g2, b2, rm2, rv2, x2, nullptr, 64);

    // layer 3: C=64 -> O=128
    compute_norms<64><<<nrm_blocks, 256>>>(x2, nrm);
    knn_kernel<64><<<knn_grid, 64>>>(x2, cand);
    rerank<64><<<rr_blocks, 256>>>(x2, nrm, cand, idx);
    prep_w<<<(128 * 64 + 255) / 256, 256>>>(w3, wp, 128, 64);
    gemm64<<<dim3(256 / 64, MTOT / 64), 256>>>(x2, wp, yz, MTOT, 64, 256);
    edge_reduce<<<MTOT, 128>>>(yz, idx, g3, b3, rm3, rv3, x3, nullptr, 128);

    // layer 4: C=128 -> O=256 (also writes transposed output)
    compute_norms<128><<<nrm_blocks, 256>>>(x3, nrm);
    knn_kernel<128><<<knn_grid, 64>>>(x3, cand);
    rerank<128><<<rr_blocks, 256>>>(x3, nrm, cand, idx);
    prep_w<<<(256 * 128 + 255) / 256, 256>>>(w4, wp, 256, 128);
    gemm64<<<dim3(512 / 64, MTOT / 64), 256>>>(x3, wp, yz, MTOT, 128, 512);
    edge_reduce<<<MTOT, 256>>>(yz, idx, g4, b4, rm4, rv4, x4, x4T, 256);

    // global max + final FC
    gmax_partial<<<dim3(B_, 16), 512>>>(x1, x2, x3, x4, part);
    gmax_final<<<B_, 512>>>(part, gmax);
    final_fc<<<dim3(4, B_), 256>>>(gmax, lw, lb, g5, b5, rm5, rv5, out);
}

// round 8
// speedup vs baseline: 1.0269x; 1.0269x over previous
#include <cuda_runtime.h>
#include <math.h>

#define B_ 8
#define NPTS 2048
#define KNB 10
#define KSEL 16
#define SPLIT 4
#define CHUNK (NPTS / SPLIT)
#define EPSV 1e-5f
#define MTOT (B_ * NPTS)

// ---------------- scratch (no allocation allowed) ----------------
__device__ float  d_x1[MTOT * 64];
__device__ float  d_x2[MTOT * 64];
__device__ float  d_x3[MTOT * 128];
__device__ float  d_x4[MTOT * 256];
__device__ float  d_yz[MTOT * 512];
__device__ int    d_idxbuf[MTOT * KNB];
__device__ int    d_cand[MTOT * SPLIT * KSEL];
__device__ double d_norm[MTOT];
__device__ float  d_wp[512 * 128];
__device__ float  d_part[B_ * 16 * 512];
__device__ float  d_gmax[B_ * 512];

// ---------------- helpers ----------------
template <int K>
__device__ __forceinline__ void insertK(float tv[K], int ti[K], float d, int m) {
    if (d <= tv[K - 1]) return;
    float cv = d; int ci = m;
#pragma unroll
    for (int p = 0; p < K; ++p) {
        if (cv > tv[p]) {
            float t = tv[p]; tv[p] = cv; cv = t;
            int u = ti[p]; ti[p] = ci; ci = u;
        }
    }
}

// ---------------- fp64 point norms: one warp per point ----------------
template <int C>
__global__ void compute_norms(const float* __restrict__ x, double* __restrict__ nrm) {
    const unsigned FULL = 0xffffffffu;
    const int gw = (blockIdx.x * 256 + threadIdx.x) >> 5;
    const int lane = threadIdx.x & 31;
    if (gw >= MTOT) return;
    const float* p = x + (size_t)gw * C;
    double s = 0.0;
#pragma unroll
    for (int c = lane; c < C; c += 32) { double v = (double)p[c]; s += v * v; }
#pragma unroll
    for (int off = 16; off; off >>= 1) s += __shfl_down_sync(FULL, s, off);
    if (lane == 0) nrm[gw] = s;
}

// ---------------- kNN pass 1 (fp32): lane = center (regs), candidate-axis split ----------------
// Block = 128 threads = 128 centers; each block scans CHUNK=512 candidates (split s).
// Grid (NPTS/128, SPLIT, B). Each thread keeps a private exact top-KSEL of its split.
template <int C>
__global__ void __launch_bounds__(128)
knn_split(const float* __restrict__ x, int* __restrict__ candout) {
    const unsigned FULL = 0xffffffffu;
    constexpr int TC = 64;  // candidates per tile
    const int b = blockIdx.z;
    const int s = blockIdx.y;
    const int n = blockIdx.x * 128 + threadIdx.x;
    const int tid = threadIdx.x;
    const int lane = tid & 31;

    __shared__ float s_tile[TC][C];
    __shared__ float s_nm[TC];

    const float* xb = x + (size_t)b * NPTS * C;

    // center into registers
    float creg[C];
    if (C % 4 == 0) {
#pragma unroll
        for (int c = 0; c < C; c += 4) {
            float4 t = *(const float4*)&xb[(size_t)n * C + c];
            creg[c] = t.x; creg[c + 1] = t.y; creg[c + 2] = t.z; creg[c + 3] = t.w;
        }
    } else {
#pragma unroll
        for (int c = 0; c < C; ++c) creg[c] = xb[(size_t)n * C + c];
    }
    float cn = 0.f;
#pragma unroll
    for (int c = 0; c < C; ++c) cn += creg[c] * creg[c];

    float tv[KSEL]; int ti[KSEL];
#pragma unroll
    for (int q = 0; q < KSEL; ++q) { tv[q] = -INFINITY; ti[q] = 0x7fffffff; }

    const int mbeg = s * CHUNK;
    for (int m0 = mbeg; m0 < mbeg + CHUNK; m0 += TC) {
        __syncthreads();
        if (C % 4 == 0) {
            constexpr int C4 = C / 4;
            constexpr int W = (C4 < 32 ? C4 : 32);
            // fused tile load + per-row norm via aligned subgroup shuffle reduce
#pragma unroll
            for (int i = tid; i < TC * C4; i += 128) {
                int r = i / C4, c4 = i % C4;
                float4 t = ((const float4*)&xb[(size_t)(m0 + r) * C])[c4];
                ((float4*)&s_tile[r][0])[c4] = t;
                float pn = t.x * t.x + t.y * t.y + t.z * t.z + t.w * t.w;
#pragma unroll
                for (int off = W / 2; off; off >>= 1)
                    pn += __shfl_down_sync(FULL, pn, off, W);
                if ((lane & (W - 1)) == 0) s_nm[r] = pn;
            }
        } else {
            for (int i = tid; i < TC * C; i += 128)
                s_tile[i / C][i % C] = xb[(size_t)(m0 + i / C) * C + i % C];
            __syncthreads();
            if (tid < TC) {
                float ss = 0.f;
#pragma unroll
                for (int c = 0; c < C; ++c) ss += s_tile[tid][c] * s_tile[tid][c];
                s_nm[tid] = ss;
            }
        }
        __syncthreads();

#pragma unroll 2
        for (int j = 0; j < TC; ++j) {
            float d;
            if (C % 4 == 0) {
                float a0 = 0.f, a1 = 0.f, a2 = 0.f, a3 = 0.f;
#pragma unroll
                for (int c = 0; c < C; c += 4) {
                    float4 t = *(const float4*)&s_tile[j][c];  // broadcast
                    a0 += creg[c + 0] * t.x;
                    a1 += creg[c + 1] * t.y;
                    a2 += creg[c + 2] * t.z;
                    a3 += creg[c + 3] * t.w;
                }
                d = 2.f * ((a0 + a1) + (a2 + a3)) - cn - s_nm[j];
            } else {
                float acc = 0.f;
#pragma unroll
                for (int c = 0; c < C; ++c) acc += creg[c] * s_tile[j][c];
                d = 2.f * acc - cn - s_nm[j];
            }
            insertK<KSEL>(tv, ti, d, m0 + j);
        }
    }

    int* out = candout + ((size_t)(b * NPTS + n) * SPLIT + s) * KSEL;
#pragma unroll
    for (int q = 0; q < KSEL; ++q) out[q] = ti[q];
}

// ---------------- kNN pass 2: fp64 exact rescore of 64 candidates, true top-10 ----------------
template <int C>
__global__ void rerank64(const float* __restrict__ x, const double* __restrict__ nrm,
                         const int* __restrict__ cand, int* __restrict__ idxout) {
    const unsigned FULL = 0xffffffffu;
    __shared__ float s_cent[8][C];
    const int warp = threadIdx.x >> 5, lane = threadIdx.x & 31;
    const int point = blockIdx.x * 8 + warp;          // global b*NPTS+n
    const int browbase = point & ~(NPTS - 1);
    const float* xb = x + (size_t)browbase * C;
    const int nloc = point - browbase;

    for (int c = lane; c < C; c += 32) s_cent[warp][c] = xb[(size_t)nloc * C + c];
    __syncwarp();

    const double np = nrm[point];
    double dv[2]; int mi[2];
#pragma unroll
    for (int t = 0; t < 2; ++t) {
        int m = cand[(size_t)point * (SPLIT * KSEL) + t * 32 + lane];
        mi[t] = m;
        const float* row = xb + (size_t)m * C;
        if (C % 4 == 0) {
            double a0 = 0.0, a1 = 0.0, a2 = 0.0, a3 = 0.0;
#pragma unroll
            for (int c = 0; c < C; c += 4) {
                float4 r = *(const float4*)&row[c];
                a0 += (double)s_cent[warp][c + 0] * (double)r.x;
                a1 += (double)s_cent[warp][c + 1] * (double)r.y;
                a2 += (double)s_cent[warp][c + 2] * (double)r.z;
                a3 += (double)s_cent[warp][c + 3] * (double)r.w;
            }
            dv[t] = 2.0 * ((a0 + a1) + (a2 + a3)) - np - nrm[browbase + m];
        } else {
            double dot = 0.0;
#pragma unroll
            for (int c = 0; c < C; ++c)
                dot += (double)s_cent[warp][c] * (double)row[c];
            dv[t] = 2.0 * dot - np - nrm[browbase + m];
        }
    }

    int* out = idxout + (size_t)point * KNB;
#pragma unroll
    for (int r = 0; r < KNB; ++r) {
        // local best among this lane's remaining 2 slots
        double v; int i_;
        if (dv[0] > dv[1] || (dv[0] == dv[1] && mi[0] < mi[1])) { v = dv[0]; i_ = mi[0]; }
        else                                                    { v = dv[1]; i_ = mi[1]; }
#pragma unroll
        for (int off = 16; off; off >>= 1) {
            double ov = __shfl_down_sync(FULL, v, off);
            int    oi = __shfl_down_sync(FULL, i_, off);
            if (ov > v || (ov == v && oi < i_)) { v = ov; i_ = oi; }
        }
        double bv = __shfl_sync(FULL, v, 0);
        int    bi = __shfl_sync(FULL, i_, 0);
        (void)bv;
        if (lane == 0) out[r] = bi;
        // invalidate winner slot (indices are globally distinct)
        if (mi[0] == bi) { dv[0] = -INFINITY; mi[0] = 0x7fffffff; }
        if (mi[1] == bi) { dv[1] = -INFINITY; mi[1] = 0x7fffffff; }
    }
}

// ---------------- weight prep: Wp = [A ; B - A] ----------------
__global__ void prep_w(const float* __restrict__ w, float* __restrict__ wp, int O, int C) {
    int i = blockIdx.x * 256 + threadIdx.x;
    if (i < O * C) {
        int o = i / C, c = i % C;
        float a = w[(size_t)o * 2 * C + c];
        wp[i] = a;
        wp[(size_t)O * C + i] = w[(size_t)o * 2 * C + C + c] - a;
    }
}

// ---------------- GEMM: Y[M,N] = X[M,K] * W[N,K]^T, 64x64 tiles, fp32 ----------------
__global__ void gemm64(const float* __restrict__ X, const float* __restrict__ W,
                       float* __restrict__ Y, int M, int K, int N) {
    __shared__ float sA[16][64];
    __shared__ float sB[16][64];
    const int tid = threadIdx.x;
    const int tx = tid & 15, ty = tid >> 4;
    const int m0 = blockIdx.y * 64, n0 = blockIdx.x * 64;
    float acc[4][4] = {};
    for (int kt = 0; kt < K; kt += 16) {
        for (int i = tid; i < 64 * 16; i += 256) {
            int r = i >> 4, kk = i & 15;
            int kg = kt + kk;
            sA[kk][r] = (kg < K) ? X[(size_t)(m0 + r) * K + kg] : 0.f;
            sB[kk][r] = (kg < K) ? W[(size_t)(n0 + r) * K + kg] : 0.f;
        }
        __syncthreads();
#pragma unroll
        for (int kk = 0; kk < 16; ++kk) {
            float4 a  = *(const float4*)&sA[kk][ty * 4];
            float4 bq = *(const float4*)&sB[kk][tx * 4];
            float av[4] = {a.x, a.y, a.z, a.w};
            float bv[4] = {bq.x, bq.y, bq.z, bq.w};
#pragma unroll
            for (int i2 = 0; i2 < 4; ++i2)
#pragma unroll
                for (int j2 = 0; j2 < 4; ++j2)
                    acc[i2][j2] += av[i2] * bv[j2];
        }
        __syncthreads();
    }
#pragma unroll
    for (int i2 = 0; i2 < 4; ++i2)
#pragma unroll
        for (int j2 = 0; j2 < 4; ++j2)
            Y[(size_t)(m0 + ty * 4 + i2) * N + n0 + tx * 4 + j2] = acc[i2][j2];
}

// ---------------- gather + reduce + BN + lrelu ----------------
__global__ void edge_reduce(const float* __restrict__ yz, const int* __restrict__ idx,
                            const float* __restrict__ gg, const float* __restrict__ bb,
                            const float* __restrict__ rm, const float* __restrict__ rv,
                            float* __restrict__ xout, float* __restrict__ outT, int O) {
    const int bn = blockIdx.x;
    const int b = bn >> 11, n = bn & 2047;
    const int o = threadIdx.x;
    __shared__ int sj[KNB];
    if (o < KNB) sj[o] = idx[(size_t)bn * KNB + o];
    __syncthreads();
    const double scale = (double)gg[o] / sqrt((double)rv[o] + 1e-5);
    const int twoO = 2 * O;
    const float z = yz[(size_t)bn * twoO + O + o];
    const int browbase = b << 11;
    float red;
    if (scale >= 0.0) {
        red = -INFINITY;
#pragma unroll
        for (int j = 0; j < KNB; ++j)
            red = fmaxf(red, yz[(size_t)(browbase + sj[j]) * twoO + o]);
    } else {
        red = INFINITY;
#pragma unroll
        for (int j = 0; j < KNB; ++j)
            red = fminf(red, yz[(size_t)(browbase + sj[j]) * twoO + o]);
    }
    double h = (((double)red + (double)z) - (double)rm[o]) * scale + (double)bb[o];
    float hf = (float)h;
    float r = hf >= 0.f ? hf : 0.2f * hf;
    xout[(size_t)bn * O + o] = r;
    if (outT) outT[((size_t)b * O + o) * NPTS + n] = r;
}

// ---------------- global max (two pass) ----------------
__global__ void gmax_partial(const float* __restrict__ x1, const float* __restrict__ x2,
                             const float* __restrict__ x3, const float* __restrict__ x4,
                             float* __restrict__ part) {
    const int b = blockIdx.x, chunk = blockIdx.y;
    const int c = threadIdx.x;  // 0..511
    const float* src; int O, off;
    if (c < 64)       { src = x1; O = 64;  off = c; }
    else if (c < 128) { src = x2; O = 64;  off = c - 64; }
    else if (c < 256) { src = x3; O = 128; off = c - 128; }
    else              { src = x4; O = 256; off = c - 256; }
    float m = -INFINITY;
    const int nbeg = chunk * 128;
    const float* p = src + ((size_t)b * NPTS + nbeg) * O + off;
    for (int n = 0; n < 128; ++n) m = fmaxf(m, p[(size_t)n * O]);
    part[((size_t)b * 16 + chunk) * 512 + c] = m;
}

__global__ void gmax_final(const float* __restrict__ part, float* __restrict__ gmax) {
    const int b = blockIdx.x, c = threadIdx.x;
    float m = -INFINITY;
    for (int ch = 0; ch < 16; ++ch)
        m = fmaxf(m, part[((size_t)b * 16 + ch) * 512 + c]);
    gmax[(size_t)b * 512 + c] = m;
}

// ---------------- final FC + BN + lrelu (fp64 accumulate) ----------------
__global__ void final_fc(const float* __restrict__ gmax, const float* __restrict__ lw,
                         const float* __restrict__ lb, const float* __restrict__ g5,
                         const float* __restrict__ b5, const float* __restrict__ rm5,
                         const float* __restrict__ rv5, float* __restrict__ out) {
    const int b = blockIdx.y;
    const int o = blockIdx.x * 256 + threadIdx.x;
    __shared__ float sg[512];
    for (int i = threadIdx.x; i < 512; i += 256) sg[i] = gmax[(size_t)b * 512 + i];
    __syncthreads();
    const float* wrow = lw + (size_t)o * 512;
    double acc = 0.0;
#pragma unroll 8
    for (int c = 0; c < 512; ++c) acc += (double)sg[c] * (double)wrow[c];
    acc += (double)lb[o];
    const double scale = (double)g5[o] / sqrt((double)rv5[o] + 1e-5);
    double h = (acc - (double)rm5[o]) * scale + (double)b5[o];
    float hf = (float)h;
    out[(size_t)b * 1024 + o] = hf >= 0.f ? hf : 0.2f * hf;
}

// ---------------- launch ----------------
extern "C" void kernel_launch(void* const* d_in, const int* in_sizes, int n_in,
                              void* d_out, int out_size) {
    const float* x    = (const float*)d_in[0];
    const float* w1   = (const float*)d_in[1];
    const float* g1   = (const float*)d_in[2];
    const float* b1   = (const float*)d_in[3];
    const float* rm1  = (const float*)d_in[4];
    const float* rv1  = (const float*)d_in[5];
    const float* w2   = (const float*)d_in[6];
    const float* g2   = (const float*)d_in[7];
    const float* b2   = (const float*)d_in[8];
    const float* rm2  = (const float*)d_in[9];
    const float* rv2  = (const float*)d_in[10];
    const float* w3   = (const float*)d_in[11];
    const float* g3   = (const float*)d_in[12];
    const float* b3   = (const float*)d_in[13];
    const float* rm3  = (const float*)d_in[14];
    const float* rv3  = (const float*)d_in[15];
    const float* w4   = (const float*)d_in[16];
    const float* g4   = (const float*)d_in[17];
    const float* b4   = (const float*)d_in[18];
    const float* rm4  = (const float*)d_in[19];
    const float* rv4  = (const float*)d_in[20];
    const float* lw   = (const float*)d_in[21];
    const float* lb   = (const float*)d_in[22];
    const float* g5   = (const float*)d_in[23];
    const float* b5   = (const float*)d_in[24];
    const float* rm5  = (const float*)d_in[25];
    const float* rv5  = (const float*)d_in[26];

    float *x1, *x2, *x3, *x4, *yz, *wp, *part, *gmax;
    int *idx, *cand;
    double* nrm;
    cudaGetSymbolAddress((void**)&x1, d_x1);
    cudaGetSymbolAddress((void**)&x2, d_x2);
    cudaGetSymbolAddress((void**)&x3, d_x3);
    cudaGetSymbolAddress((void**)&x4, d_x4);
    cudaGetSymbolAddress((void**)&yz, d_yz);
    cudaGetSymbolAddress((void**)&idx, d_idxbuf);
    cudaGetSymbolAddress((void**)&cand, d_cand);
    cudaGetSymbolAddress((void**)&nrm, d_norm);
    cudaGetSymbolAddress((void**)&wp, d_wp);
    cudaGetSymbolAddress((void**)&part, d_part);
    cudaGetSymbolAddress((void**)&gmax, d_gmax);

    float* out = (float*)d_out;
    float* x4T = out + B_ * 1024;

    const dim3 knn_grid(NPTS / 128, SPLIT, B_);
    const int nrm_blocks = (MTOT * 32 + 255) / 256;
    const int rr_blocks = MTOT / 8;

    // layer 1: C=5 -> O=64
    compute_norms<5><<<nrm_blocks, 256>>>(x, nrm);
    knn_split<5><<<knn_grid, 128>>>(x, cand);
    rerank64<5><<<rr_blocks, 256>>>(x, nrm, cand, idx);
    prep_w<<<(64 * 5 + 255) / 256, 256>>>(w1, wp, 64, 5);
    gemm64<<<dim3(128 / 64, MTOT / 64), 256>>>(x, wp, yz, MTOT, 5, 128);
    edge_reduce<<<MTOT, 64>>>(yz, idx, g1, b1, rm1, rv1, x1, nullptr, 64);

    // layer 2: C=64 -> O=64
    compute_norms<64><<<nrm_blocks, 256>>>(x1, nrm);
    knn_split<64><<<knn_grid, 128>>>(x1, cand);
    rerank64<64><<<rr_blocks, 256>>>(x1, nrm, cand, idx);
    prep_w<<<(64 * 64 + 255) / 256, 256>>>(w2, wp, 64, 64);
    gemm64<<<dim3(128 / 64, MTOT / 64), 256>>>(x1, wp, yz, MTOT, 64, 128);
    edge_reduce<<<MTOT, 64>>>(yz, idx, g2, b2, rm2, rv2, x2, nullptr, 64);

    // layer 3: C=64 -> O=128
    compute_norms<64><<<nrm_blocks, 256>>>(x2, nrm);
    knn_split<64><<<knn_grid, 128>>>(x2, cand);
    rerank64<64><<<rr_blocks, 256>>>(x2, nrm, cand, idx);
    prep_w<<<(128 * 64 + 255) / 256, 256>>>(w3, wp, 128, 64);
    gemm64<<<dim3(256 / 64, MTOT / 64), 256>>>(x2, wp, yz, MTOT, 64, 256);
    edge_reduce<<<MTOT, 128>>>(yz, idx, g3, b3, rm3, rv3, x3, nullptr, 128);

    // layer 4: C=128 -> O=256 (also writes transposed output)
    compute_norms<128><<<nrm_blocks, 256>>>(x3, nrm);
    knn_split<128><<<knn_grid, 128>>>(x3, cand);
    rerank64<128><<<rr_blocks, 256>>>(x3, nrm, cand, idx);
    prep_w<<<(256 * 128 + 255) / 256, 256>>>(w4, wp, 256, 128);
    gemm64<<<dim3(512 / 64, MTOT / 64), 256>>>(x3, wp, yz, MTOT, 128, 512);
    edge_reduce<<<MTOT, 256>>>(yz, idx, g4, b4, rm4, rv4, x4, x4T, 256);

    // global max + final FC
    gmax_partial<<<dim3(B_, 16), 512>>>(x1, x2, x3, x4, part);
    gmax_final<<<B_, 512>>>(part, gmax);
    final_fc<<<dim3(4, B_), 256>>>(gmax, lw, lb, g5, b5, rm5, rv5, out);
}

// round 9
// speedup vs baseline: 1.0638x; 1.0359x over previous
#include <cuda_runtime.h>
#include <math.h>

#define B_ 8
#define NPTS 2048
#define KNB 10
#define KSEL 16
#define EPSV 1e-5f
#define MTOT (B_ * NPTS)

// ---------------- scratch (no allocation allowed) ----------------
__device__ float  d_x1[MTOT * 64];
__device__ float  d_x2[MTOT * 64];
__device__ float  d_x3[MTOT * 128];
__device__ float  d_x4[MTOT * 256];
__device__ float  d_yz[MTOT * 512];
__device__ float  d_dist[(size_t)MTOT * NPTS];   // 134 MB ranking scores
__device__ int    d_idxbuf[MTOT * KNB];
__device__ int    d_cand[MTOT * KSEL];
__device__ double d_norm[MTOT];
__device__ float  d_normf[MTOT];
__device__ float  d_wp[512 * 128];
__device__ float  d_part[B_ * 16 * 512];
__device__ float  d_gmax[B_ * 512];

// ---------------- helpers ----------------
template <int K>
__device__ __forceinline__ void insertK(float tv[K], int ti[K], float d, int m) {
    if (d <= tv[K - 1]) return;
    float cv = d; int ci = m;
#pragma unroll
    for (int p = 0; p < K; ++p) {
        if (cv > tv[p]) {
            float t = tv[p]; tv[p] = cv; cv = t;
            int u = ti[p]; ti[p] = ci; ci = u;
        }
    }
}

template <int K>
__device__ __forceinline__ void topk_merge_write(float tv[K], int ti[K],
                                                 int* __restrict__ out, int lane) {
    const unsigned FULL = 0xffffffffu;
#pragma unroll
    for (int r = 0; r < K; ++r) {
        float hv = tv[0]; int hi = ti[0];
        float v = hv; int i = hi;
#pragma unroll
        for (int off = 16; off; off >>= 1) {
            float ov = __shfl_down_sync(FULL, v, off);
            int   oi = __shfl_down_sync(FULL, i, off);
            if (ov > v || (ov == v && oi < i)) { v = ov; i = oi; }
        }
        float bv = __shfl_sync(FULL, v, 0);
        int   bi = __shfl_sync(FULL, i, 0);
        if (lane == 0) out[r] = bi;
        if (hv == bv && hi == bi) {  // this lane won: pop head
#pragma unroll
            for (int q = 0; q < K - 1; ++q) { tv[q] = tv[q + 1]; ti[q] = ti[q + 1]; }
            tv[K - 1] = -INFINITY; ti[K - 1] = 0x7fffffff;
        }
    }
}

// ---------------- point norms: one warp per point; fp64 (rerank) + fp32 (pass-1) ----------------
template <int C>
__global__ void compute_norms(const float* __restrict__ x, double* __restrict__ nrm,
                              float* __restrict__ nrmf) {
    const unsigned FULL = 0xffffffffu;
    const int gw = (blockIdx.x * 256 + threadIdx.x) >> 5;
    const int lane = threadIdx.x & 31;
    if (gw >= MTOT) return;
    const float* p = x + (size_t)gw * C;
    double s = 0.0;
#pragma unroll
    for (int c = lane; c < C; c += 32) { double v = (double)p[c]; s += v * v; }
#pragma unroll
    for (int off = 16; off; off >>= 1) s += __shfl_down_sync(FULL, s, off);
    if (lane == 0) { nrm[gw] = s; nrmf[gw] = (float)s; }
}

// ---------------- distance GEMM: r[n][m] = 2 * <x_n, x_m> - ||x_m||^2 ----------------
// 64x64 tiles per block, 256 threads, 4x4 micro-tile. Grid (NPTS/64, NPTS/64, B).
__global__ void dist_gemm(const float* __restrict__ X, const float* __restrict__ nf,
                          float* __restrict__ D, int K) {
    __shared__ float sA[16][64];
    __shared__ float sB[16][64];
    const int b = blockIdx.z;
    const float* Xb = X + (size_t)b * NPTS * K;
    const int tid = threadIdx.x;
    const int tx = tid & 15, ty = tid >> 4;
    const int n0 = blockIdx.y * 64, m0 = blockIdx.x * 64;
    float acc[4][4] = {};
    for (int kt = 0; kt < K; kt += 16) {
        for (int i = tid; i < 64 * 16; i += 256) {
            int r = i >> 4, kk = i & 15;
            int kg = kt + kk;
            sA[kk][r] = (kg < K) ? Xb[(size_t)(n0 + r) * K + kg] : 0.f;
            sB[kk][r] = (kg < K) ? Xb[(size_t)(m0 + r) * K + kg] : 0.f;
        }
        __syncthreads();
#pragma unroll
        for (int kk = 0; kk < 16; ++kk) {
            float4 a  = *(const float4*)&sA[kk][ty * 4];
            float4 bq = *(const float4*)&sB[kk][tx * 4];
            float av[4] = {a.x, a.y, a.z, a.w};
            float bv[4] = {bq.x, bq.y, bq.z, bq.w};
#pragma unroll
            for (int i2 = 0; i2 < 4; ++i2)
#pragma unroll
                for (int j2 = 0; j2 < 4; ++j2)
                    acc[i2][j2] += av[i2] * bv[j2];
        }
        __syncthreads();
    }
    const float* nfb = nf + (size_t)b * NPTS;
#pragma unroll
    for (int j2 = 0; j2 < 4; ++j2) {
        const float nm = nfb[m0 + tx * 4 + j2];
#pragma unroll
        for (int i2 = 0; i2 < 4; ++i2)
            D[((size_t)b * NPTS + n0 + ty * 4 + i2) * NPTS + m0 + tx * 4 + j2] =
                2.f * acc[i2][j2] - nm;
    }
}

// ---------------- selection: warp per row, top-16 of 2048 scores ----------------
__global__ void __launch_bounds__(128)
select16(const float* __restrict__ D, int* __restrict__ cand) {
    const int warp = threadIdx.x >> 5, lane = threadIdx.x & 31;
    const int point = blockIdx.x * 4 + warp;   // global b*NPTS+n
    const float* row = D + (size_t)point * NPTS;

    float tv[KSEL]; int ti[KSEL];
#pragma unroll
    for (int q = 0; q < KSEL; ++q) { tv[q] = -INFINITY; ti[q] = 0x7fffffff; }

#pragma unroll 4
    for (int t = 0; t < NPTS / 32; ++t) {
        const int m = t * 32 + lane;
        insertK<KSEL>(tv, ti, row[m], m);
    }

    topk_merge_write<KSEL>(tv, ti, cand + (size_t)point * KSEL, lane);
}

// ---------------- kNN pass 2: fp64 exact rescore of top-16, keep true top-10 ----------------
template <int C>
__global__ void rerank(const float* __restrict__ x, const double* __restrict__ nrm,
                       const int* __restrict__ cand, int* __restrict__ idxout) {
    const unsigned FULL = 0xffffffffu;
    __shared__ float s_cent[8][C];
    const int warp = threadIdx.x >> 5, lane = threadIdx.x & 31;
    const int point = blockIdx.x * 8 + warp;          // global b*NPTS+n
    const int browbase = point & ~(NPTS - 1);
    const float* xb = x + (size_t)browbase * C;
    const int nloc = point - browbase;

    for (int c = lane; c < C; c += 32) s_cent[warp][c] = xb[(size_t)nloc * C + c];
    __syncwarp();

    double d = -INFINITY;
    int mi = 0x7fffffff;
    if (lane < KSEL) {
        mi = cand[(size_t)point * KSEL + lane];
        const float* row = xb + (size_t)mi * C;
        if (C % 4 == 0) {
            double a0 = 0.0, a1 = 0.0, a2 = 0.0, a3 = 0.0;
#pragma unroll
            for (int c = 0; c < C; c += 4) {
                float4 r = *(const float4*)&row[c];
                a0 += (double)s_cent[warp][c + 0] * (double)r.x;
                a1 += (double)s_cent[warp][c + 1] * (double)r.y;
                a2 += (double)s_cent[warp][c + 2] * (double)r.z;
                a3 += (double)s_cent[warp][c + 3] * (double)r.w;
            }
            d = 2.0 * ((a0 + a1) + (a2 + a3)) - nrm[point] - nrm[browbase + mi];
        } else {
            double dot = 0.0;
#pragma unroll
            for (int c = 0; c < C; ++c)
                dot += (double)s_cent[warp][c] * (double)row[c];
            d = 2.0 * dot - nrm[point] - nrm[browbase + mi];
        }
    }

    int* out = idxout + (size_t)point * KNB;
#pragma unroll
    for (int r = 0; r < KNB; ++r) {
        double v = d; int i_ = mi;
#pragma unroll
        for (int off = 16; off; off >>= 1) {
            double ov = __shfl_down_sync(FULL, v, off);
            int    oi = __shfl_down_sync(FULL, i_, off);
            if (ov > v || (ov == v && oi < i_)) { v = ov; i_ = oi; }
        }
        double bv = __shfl_sync(FULL, v, 0);
        int    bi = __shfl_sync(FULL, i_, 0);
        if (lane == 0) out[r] = bi;
        if (d == bv && mi == bi) d = -INFINITY;
    }
}

// ---------------- weight prep: Wp = [A ; B - A] ----------------
__global__ void prep_w(const float* __restrict__ w, float* __restrict__ wp, int O, int C) {
    int i = blockIdx.x * 256 + threadIdx.x;
    if (i < O * C) {
        int o = i / C, c = i % C;
        float a = w[(size_t)o * 2 * C + c];
        wp[i] = a;
        wp[(size_t)O * C + i] = w[(size_t)o * 2 * C + C + c] - a;
    }
}

// ---------------- GEMM: Y[M,N] = X[M,K] * W[N,K]^T, 64x64 tiles, fp32 ----------------
__global__ void gemm64(const float* __restrict__ X, const float* __restrict__ W,
                       float* __restrict__ Y, int M, int K, int N) {
    __shared__ float sA[16][64];
    __shared__ float sB[16][64];
    const int tid = threadIdx.x;
    const int tx = tid & 15, ty = tid >> 4;
    const int m0 = blockIdx.y * 64, n0 = blockIdx.x * 64;
    float acc[4][4] = {};
    for (int kt = 0; kt < K; kt += 16) {
        for (int i = tid; i < 64 * 16; i += 256) {
            int r = i >> 4, kk = i & 15;
            int kg = kt + kk;
            sA[kk][r] = (kg < K) ? X[(size_t)(m0 + r) * K + kg] : 0.f;
            sB[kk][r] = (kg < K) ? W[(size_t)(n0 + r) * K + kg] : 0.f;
        }
        __syncthreads();
#pragma unroll
        for (int kk = 0; kk < 16; ++kk) {
            float4 a  = *(const float4*)&sA[kk][ty * 4];
            float4 bq = *(const float4*)&sB[kk][tx * 4];
            float av[4] = {a.x, a.y, a.z, a.w};
            float bv[4] = {bq.x, bq.y, bq.z, bq.w};
#pragma unroll
            for (int i2 = 0; i2 < 4; ++i2)
#pragma unroll
                for (int j2 = 0; j2 < 4; ++j2)
                    acc[i2][j2] += av[i2] * bv[j2];
        }
        __syncthreads();
    }
#pragma unroll
    for (int i2 = 0; i2 < 4; ++i2)
#pragma unroll
        for (int j2 = 0; j2 < 4; ++j2)
            Y[(size_t)(m0 + ty * 4 + i2) * N + n0 + tx * 4 + j2] = acc[i2][j2];
}

// ---------------- gather + reduce + BN + lrelu ----------------
__global__ void edge_reduce(const float* __restrict__ yz, const int* __restrict__ idx,
                            const float* __restrict__ gg, const float* __restrict__ bb,
                            const float* __restrict__ rm, const float* __restrict__ rv,
                            float* __restrict__ xout, float* __restrict__ outT, int O) {
    const int bn = blockIdx.x;
    const int b = bn >> 11, n = bn & 2047;
    const int o = threadIdx.x;
    __shared__ int sj[KNB];
    if (o < KNB) sj[o] = idx[(size_t)bn * KNB + o];
    __syncthreads();
    const double scale = (double)gg[o] / sqrt((double)rv[o] + 1e-5);
    const int twoO = 2 * O;
    const float z = yz[(size_t)bn * twoO + O + o];
    const int browbase = b << 11;
    float red;
    if (scale >= 0.0) {
        red = -INFINITY;
#pragma unroll
        for (int j = 0; j < KNB; ++j)
            red = fmaxf(red, yz[(size_t)(browbase + sj[j]) * twoO + o]);
    } else {
        red = INFINITY;
#pragma unroll
        for (int j = 0; j < KNB; ++j)
            red = fminf(red, yz[(size_t)(browbase + sj[j]) * twoO + o]);
    }
    double h = (((double)red + (double)z) - (double)rm[o]) * scale + (double)bb[o];
    float hf = (float)h;
    float r = hf >= 0.f ? hf : 0.2f * hf;
    xout[(size_t)bn * O + o] = r;
    if (outT) outT[((size_t)b * O + o) * NPTS + n] = r;
}

// ---------------- global max (two pass) ----------------
__global__ void gmax_partial(const float* __restrict__ x1, const float* __restrict__ x2,
                             const float* __restrict__ x3, const float* __restrict__ x4,
                             float* __restrict__ part) {
    const int b = blockIdx.x, chunk = blockIdx.y;
    const int c = threadIdx.x;  // 0..511
    const float* src; int O, off;
    if (c < 64)       { src = x1; O = 64;  off = c; }
    else if (c < 128) { src = x2; O = 64;  off = c - 64; }
    else if (c < 256) { src = x3; O = 128; off = c - 128; }
    else              { src = x4; O = 256; off = c - 256; }
    float m = -INFINITY;
    const int nbeg = chunk * 128;
    const float* p = src + ((size_t)b * NPTS + nbeg) * O + off;
    for (int n = 0; n < 128; ++n) m = fmaxf(m, p[(size_t)n * O]);
    part[((size_t)b * 16 + chunk) * 512 + c] = m;
}

__global__ void gmax_final(const float* __restrict__ part, float* __restrict__ gmax) {
    const int b = blockIdx.x, c = threadIdx.x;
    float m = -INFINITY;
    for (int ch = 0; ch < 16; ++ch)
        m = fmaxf(m, part[((size_t)b * 16 + ch) * 512 + c]);
    gmax[(size_t)b * 512 + c] = m;
}

// ---------------- final FC + BN + lrelu (fp64 accumulate) ----------------
__global__ void final_fc(const float* __restrict__ gmax, const float* __restrict__ lw,
                         const float* __restrict__ lb, const float* __restrict__ g5,
                         const float* __restrict__ b5, const float* __restrict__ rm5,
                         const float* __restrict__ rv5, float* __restrict__ out) {
    const int b = blockIdx.y;
    const int o = blockIdx.x * 256 + threadIdx.x;
    __shared__ float sg[512];
    for (int i = threadIdx.x; i < 512; i += 256) sg[i] = gmax[(size_t)b * 512 + i];
    __syncthreads();
    const float* wrow = lw + (size_t)o * 512;
    double acc = 0.0;
#pragma unroll 8
    for (int c = 0; c < 512; ++c) acc += (double)sg[c] * (double)wrow[c];
    acc += (double)lb[o];
    const double scale = (double)g5[o] / sqrt((double)rv5[o] + 1e-5);
    double h = (acc - (double)rm5[o]) * scale + (double)b5[o];
    float hf = (float)h;
    out[(size_t)b * 1024 + o] = hf >= 0.f ? hf : 0.2f * hf;
}

// ---------------- launch ----------------
extern "C" void kernel_launch(void* const* d_in, const int* in_sizes, int n_in,
                              void* d_out, int out_size) {
    const float* x    = (const float*)d_in[0];
    const float* w1   = (const float*)d_in[1];
    const float* g1   = (const float*)d_in[2];
    const float* b1   = (const float*)d_in[3];
    const float* rm1  = (const float*)d_in[4];
    const float* rv1  = (const float*)d_in[5];
    const float* w2   = (const float*)d_in[6];
    const float* g2   = (const float*)d_in[7];
    const float* b2   = (const float*)d_in[8];
    const float* rm2  = (const float*)d_in[9];
    const float* rv2  = (const float*)d_in[10];
    const float* w3   = (const float*)d_in[11];
    const float* g3   = (const float*)d_in[12];
    const float* b3   = (const float*)d_in[13];
    const float* rm3  = (const float*)d_in[14];
    const float* rv3  = (const float*)d_in[15];
    const float* w4   = (const float*)d_in[16];
    const float* g4   = (const float*)d_in[17];
    const float* b4   = (const float*)d_in[18];
    const float* rm4  = (const float*)d_in[19];
    const float* rv4  = (const float*)d_in[20];
    const float* lw   = (const float*)d_in[21];
    const float* lb   = (const float*)d_in[22];
    const float* g5   = (const float*)d_in[23];
    const float* b5   = (const float*)d_in[24];
    const float* rm5  = (const float*)d_in[25];
    const float* rv5  = (const float*)d_in[26];

    float *x1, *x2, *x3, *x4, *yz, *wp, *part, *gmax, *dist, *nrmf;
    int *idx, *cand;
    double* nrm;
    cudaGetSymbolAddress((void**)&x1, d_x1);
    cudaGetSymbolAddress((void**)&x2, d_x2);
    cudaGetSymbolAddress((void**)&x3, d_x3);
    cudaGetSymbolAddress((void**)&x4, d_x4);
    cudaGetSymbolAddress((void**)&yz, d_yz);
    cudaGetSymbolAddress((void**)&dist, d_dist);
    cudaGetSymbolAddress((void**)&idx, d_idxbuf);
    cudaGetSymbolAddress((void**)&cand, d_cand);
    cudaGetSymbolAddress((void**)&nrm, d_norm);
    cudaGetSymbolAddress((void**)&nrmf, d_normf);
    cudaGetSymbolAddress((void**)&wp, d_wp);
    cudaGetSymbolAddress((void**)&part, d_part);
    cudaGetSymbolAddress((void**)&gmax, d_gmax);

    float* out = (float*)d_out;
    float* x4T = out + B_ * 1024;

    const dim3 dist_grid(NPTS / 64, NPTS / 64, B_);
    const int nrm_blocks = (MTOT * 32 + 255) / 256;
    const int sel_blocks = MTOT / 4;
    const int rr_blocks = MTOT / 8;

    // layer 1: C=5 -> O=64   (select16 placed at app-launch slot 4 for ncu capture)
    compute_norms<5><<<nrm_blocks, 256>>>(x, nrm, nrmf);
    dist_gemm<<<dist_grid, 256>>>(x, nrmf, dist, 5);
    prep_w<<<(64 * 5 + 255) / 256, 256>>>(w1, wp, 64, 5);
    select16<<<sel_blocks, 128>>>(dist, cand);
    rerank<5><<<rr_blocks, 256>>>(x, nrm, cand, idx);
    gemm64<<<dim3(128 / 64, MTOT / 64), 256>>>(x, wp, yz, MTOT, 5, 128);
    edge_reduce<<<MTOT, 64>>>(yz, idx, g1, b1, rm1, rv1, x1, nullptr, 64);

    // layer 2: C=64 -> O=64
    compute_norms<64><<<nrm_blocks, 256>>>(x1, nrm, nrmf);
    dist_gemm<<<dist_grid, 256>>>(x1, nrmf, dist, 64);
    select16<<<sel_blocks, 128>>>(dist, cand);
    rerank<64><<<rr_blocks, 256>>>(x1, nrm, cand, idx);
    prep_w<<<(64 * 64 + 255) / 256, 256>>>(w2, wp, 64, 64);
    gemm64<<<dim3(128 / 64, MTOT / 64), 256>>>(x1, wp, yz, MTOT, 64, 128);
    edge_reduce<<<MTOT, 64>>>(yz, idx, g2, b2, rm2, rv2, x2, nullptr, 64);

    // layer 3: C=64 -> O=128
    compute_norms<64><<<nrm_blocks, 256>>>(x2, nrm, nrmf);
    dist_gemm<<<dist_grid, 256>>>(x2, nrmf, dist, 64);
    select16<<<sel_blocks, 128>>>(dist, cand);
    rerank<64><<<rr_blocks, 256>>>(x2, nrm, cand, idx);
    prep_w<<<(128 * 64 + 255) / 256, 256>>>(w3, wp, 128, 64);
    gemm64<<<dim3(256 / 64, MTOT / 64), 256>>>(x2, wp, yz, MTOT, 64, 256);
    edge_reduce<<<MTOT, 128>>>(yz, idx, g3, b3, rm3, rv3, x3, nullptr, 128);

    // layer 4: C=128 -> O=256 (also writes transposed output)
    compute_norms<128><<<nrm_blocks, 256>>>(x3, nrm, nrmf);
    dist_gemm<<<dist_grid, 256>>>(x3, nrmf, dist, 128);
    select16<<<sel_blocks, 128>>>(dist, cand);
    rerank<128><<<rr_blocks, 256>>>(x3, nrm, cand, idx);
    prep_w<<<(256 * 128 + 255) / 256, 256>>>(w4, wp, 256, 128);
    gemm64<<<dim3(512 / 64, MTOT / 64), 256>>>(x3, wp, yz, MTOT, 128, 512);
    edge_reduce<<<MTOT, 256>>>(yz, idx, g4, b4, rm4, rv4, x4, x4T, 256);

    // global max + final FC
    gmax_partial<<<dim3(B_, 16), 512>>>(x1, x2, x3, x4, part);
    gmax_final<<<B_, 512>>>(part, gmax);
    final_fc<<<dim3(4, B_), 256>>>(gmax, lw, lb, g5, b5, rm5, rv5, out);
}

// round 10
// speedup vs baseline: 1.5410x; 1.4486x over previous
#include <cuda_runtime.h>
#include <math.h>

#define B_ 8
#define NPTS 2048
#define KNB 10
#define KSEL 16
#define EPSV 1e-5f
#define MTOT (B_ * NPTS)

// ---------------- scratch (no allocation allowed) ----------------
__device__ float  d_x1[MTOT * 64];
__device__ float  d_x2[MTOT * 64];
__device__ float  d_x3[MTOT * 128];
__device__ float  d_x4[MTOT * 256];
__device__ float  d_yz[MTOT * 512];
__device__ float  d_dist[(size_t)MTOT * NPTS];   // 134 MB ranking scores
__device__ int    d_idxbuf[MTOT * KNB];
__device__ int    d_cand[MTOT * KSEL];
__device__ double d_norm[MTOT];
__device__ float  d_normf[MTOT];
__device__ float  d_wp[512 * 128];
__device__ float  d_part[B_ * 16 * 512];
__device__ float  d_gmax[B_ * 512];

// ---------------- point norms: one warp per point; fp64 (rerank) + fp32 (pass-1) ----------------
template <int C>
__global__ void compute_norms(const float* __restrict__ x, double* __restrict__ nrm,
                              float* __restrict__ nrmf) {
    const unsigned FULL = 0xffffffffu;
    const int gw = (blockIdx.x * 256 + threadIdx.x) >> 5;
    const int lane = threadIdx.x & 31;
    if (gw >= MTOT) return;
    const float* p = x + (size_t)gw * C;
    double s = 0.0;
#pragma unroll
    for (int c = lane; c < C; c += 32) { double v = (double)p[c]; s += v * v; }
#pragma unroll
    for (int off = 16; off; off >>= 1) s += __shfl_down_sync(FULL, s, off);
    if (lane == 0) { nrm[gw] = s; nrmf[gw] = (float)s; }
}

// ---------------- 128x128 tile GEMM, 8x8 microtile, 256 threads ----------------
// DIST=true : Y[(bz*NPTS + n)*NPTS + m] = 2*<x_n, x_m> - ||x_m||^2  (A==B==Xb, grid (16,16,B))
// DIST=false: Y[n*N + m] = <X_n, W_m>                                (grid (N/128, MTOT/128, 1))
template <int K, bool DIST>
__global__ void __launch_bounds__(256)
gemm128(const float* __restrict__ A, const float* __restrict__ Bw,
        const float* __restrict__ nf, float* __restrict__ Y, int N) {
    __shared__ float sA[16][132];
    __shared__ float sB[16][132];
    const int bz = blockIdx.z;
    const float* Ab = A + (DIST ? (size_t)bz * NPTS * K : (size_t)0);
    const float* Bb = DIST ? Ab : Bw;
    const int rt0 = blockIdx.y * 128;   // output rows (n)
    const int ct0 = blockIdx.x * 128;   // output cols (m)
    const int tid = threadIdx.x;
    const int tx = tid & 15, ty = tid >> 4;

    float acc[8][8] = {};

    for (int kt = 0; kt < K; kt += 16) {
        if (K % 4 == 0) {
#pragma unroll
            for (int i = tid; i < 512; i += 256) {
                int r = i >> 2, kq = (i & 3) << 2;
                int kg = kt + kq;
                float4 t = make_float4(0.f, 0.f, 0.f, 0.f);
                float4 u = make_float4(0.f, 0.f, 0.f, 0.f);
                if (kg < K) {
                    t = *(const float4*)&Ab[(size_t)(rt0 + r) * K + kg];
                    u = *(const float4*)&Bb[(size_t)(ct0 + r) * K + kg];
                }
                sA[kq + 0][r] = t.x; sA[kq + 1][r] = t.y;
                sA[kq + 2][r] = t.z; sA[kq + 3][r] = t.w;
                sB[kq + 0][r] = u.x; sB[kq + 1][r] = u.y;
                sB[kq + 2][r] = u.z; sB[kq + 3][r] = u.w;
            }
        } else {
            for (int i = tid; i < 2048; i += 256) {
                int r = i >> 4, k = i & 15;
                int kg = kt + k;
                sA[k][r] = (kg < K) ? Ab[(size_t)(rt0 + r) * K + kg] : 0.f;
                sB[k][r] = (kg < K) ? Bb[(size_t)(ct0 + r) * K + kg] : 0.f;
            }
        }
        __syncthreads();
#pragma unroll
        for (int kk = 0; kk < 16; ++kk) {
            float a[8], bb[8];
            *(float4*)&a[0]  = *(const float4*)&sA[kk][ty * 8];
            *(float4*)&a[4]  = *(const float4*)&sA[kk][ty * 8 + 4];
            *(float4*)&bb[0] = *(const float4*)&sB[kk][tx * 8];
            *(float4*)&bb[4] = *(const float4*)&sB[kk][tx * 8 + 4];
#pragma unroll
            for (int i2 = 0; i2 < 8; ++i2)
#pragma unroll
                for (int j2 = 0; j2 < 8; ++j2)
                    acc[i2][j2] += a[i2] * bb[j2];
        }
        __syncthreads();
    }

    if (DIST) {
        const float* nfb = nf + (size_t)bz * NPTS;
        float nmv[8];
        *(float4*)&nmv[0] = *(const float4*)&nfb[ct0 + tx * 8];
        *(float4*)&nmv[4] = *(const float4*)&nfb[ct0 + tx * 8 + 4];
#pragma unroll
        for (int i2 = 0; i2 < 8; ++i2) {
            float4 o0, o1;
            o0.x = 2.f * acc[i2][0] - nmv[0]; o0.y = 2.f * acc[i2][1] - nmv[1];
            o0.z = 2.f * acc[i2][2] - nmv[2]; o0.w = 2.f * acc[i2][3] - nmv[3];
            o1.x = 2.f * acc[i2][4] - nmv[4]; o1.y = 2.f * acc[i2][5] - nmv[5];
            o1.z = 2.f * acc[i2][6] - nmv[6]; o1.w = 2.f * acc[i2][7] - nmv[7];
            float* dst = Y + ((size_t)bz * NPTS + rt0 + ty * 8 + i2) * NPTS + ct0 + tx * 8;
            *(float4*)&dst[0] = o0;
            *(float4*)&dst[4] = o1;
        }
    } else {
#pragma unroll
        for (int i2 = 0; i2 < 8; ++i2) {
            float* dst = Y + (size_t)(rt0 + ty * 8 + i2) * N + ct0 + tx * 8;
            *(float4*)&dst[0] = make_float4(acc[i2][0], acc[i2][1], acc[i2][2], acc[i2][3]);
            *(float4*)&dst[4] = make_float4(acc[i2][4], acc[i2][5], acc[i2][6], acc[i2][7]);
        }
    }
}

// ---------------- selection: warp per row; per-lane top-4 cache + argmax pops + exact rescan ----
__device__ __forceinline__ void ins4(float v[4], int id[4], float d, int m) {
    if (d > v[3]) {
        float cv = d; int ci = m;
#pragma unroll
        for (int p = 0; p < 4; ++p) {
            if (cv > v[p]) {
                float t = v[p]; v[p] = cv; cv = t;
                int u = id[p]; id[p] = ci; ci = u;
            }
        }
    }
}

__global__ void __launch_bounds__(128)
select16(const float* __restrict__ D, int* __restrict__ cand) {
    const unsigned FULL = 0xffffffffu;
    const int warp = threadIdx.x >> 5, lane = threadIdx.x & 31;
    const int point = blockIdx.x * 4 + warp;   // global b*NPTS+n
    const float* row = D + (size_t)point * NPTS;

    float v[4]; int id[4];
#pragma unroll
    for (int q = 0; q < 4; ++q) { v[q] = -INFINITY; id[q] = 0x7fffffff; }
    unsigned long long used = 0ull;   // bit t => index t*32+lane already emitted

#pragma unroll 8
    for (int t = 0; t < NPTS / 32; ++t)
        ins4(v, id, row[t * 32 + lane], t * 32 + lane);

    int* out = cand + (size_t)point * KSEL;
    for (int r = 0; r < KSEL; ++r) {
        if (v[0] == -INFINITY) {
            // cache exhausted: rescan unused values of this lane (exact refill)
            for (int t = 0; t < NPTS / 32; ++t) {
                if ((used >> t) & 1ull) continue;
                ins4(v, id, row[t * 32 + lane], t * 32 + lane);
            }
        }
        float vv = v[0]; int ii = id[0];
#pragma unroll
        for (int off = 16; off; off >>= 1) {
            float ov = __shfl_down_sync(FULL, vv, off);
            int   oi = __shfl_down_sync(FULL, ii, off);
            if (ov > vv || (ov == vv && oi < ii)) { vv = ov; ii = oi; }
        }
        int bi = __shfl_sync(FULL, ii, 0);
        if (lane == 0) out[r] = bi;
        if (id[0] == bi) {   // this lane owns the winner (indices unique per lane)
            used |= 1ull << ((id[0] - lane) >> 5);
#pragma unroll
            for (int q = 0; q < 3; ++q) { v[q] = v[q + 1]; id[q] = id[q + 1]; }
            v[3] = -INFINITY; id[3] = 0x7fffffff;
        }
    }
}

// ---------------- kNN pass 2: fp64 exact rescore of top-16, keep true top-10 ----------------
template <int C>
__global__ void rerank(const float* __restrict__ x, const double* __restrict__ nrm,
                       const int* __restrict__ cand, int* __restrict__ idxout) {
    const unsigned FULL = 0xffffffffu;
    __shared__ float s_cent[8][C];
    const int warp = threadIdx.x >> 5, lane = threadIdx.x & 31;
    const int point = blockIdx.x * 8 + warp;          // global b*NPTS+n
    const int browbase = point & ~(NPTS - 1);
    const float* xb = x + (size_t)browbase * C;
    const int nloc = point - browbase;

    for (int c = lane; c < C; c += 32) s_cent[warp][c] = xb[(size_t)nloc * C + c];
    __syncwarp();

    double d = -INFINITY;
    int mi = 0x7fffffff;
    if (lane < KSEL) {
        mi = cand[(size_t)point * KSEL + lane];
        const float* row = xb + (size_t)mi * C;
        if (C % 4 == 0) {
            double a0 = 0.0, a1 = 0.0, a2 = 0.0, a3 = 0.0;
#pragma unroll
            for (int c = 0; c < C; c += 4) {
                float4 r = *(const float4*)&row[c];
                a0 += (double)s_cent[warp][c + 0] * (double)r.x;
                a1 += (double)s_cent[warp][c + 1] * (double)r.y;
                a2 += (double)s_cent[warp][c + 2] * (double)r.z;
                a3 += (double)s_cent[warp][c + 3] * (double)r.w;
            }
            d = 2.0 * ((a0 + a1) + (a2 + a3)) - nrm[point] - nrm[browbase + mi];
        } else {
            double dot = 0.0;
#pragma unroll
            for (int c = 0; c < C; ++c)
                dot += (double)s_cent[warp][c] * (double)row[c];
            d = 2.0 * dot - nrm[point] - nrm[browbase + mi];
        }
    }

    int* out = idxout + (size_t)point * KNB;
#pragma unroll
    for (int r = 0; r < KNB; ++r) {
        double v = d; int i_ = mi;
#pragma unroll
        for (int off = 16; off; off >>= 1) {
            double ov = __shfl_down_sync(FULL, v, off);
            int    oi = __shfl_down_sync(FULL, i_, off);
            if (ov > v || (ov == v && oi < i_)) { v = ov; i_ = oi; }
        }
        double bv = __shfl_sync(FULL, v, 0);
        int    bi = __shfl_sync(FULL, i_, 0);
        if (lane == 0) out[r] = bi;
        if (d == bv && mi == bi) d = -INFINITY;
    }
}

// ---------------- weight prep: Wp = [A ; B - A] ----------------
__global__ void prep_w(const float* __restrict__ w, float* __restrict__ wp, int O, int C) {
    int i = blockIdx.x * 256 + threadIdx.x;
    if (i < O * C) {
        int o = i / C, c = i % C;
        float a = w[(size_t)o * 2 * C + c];
        wp[i] = a;
        wp[(size_t)O * C + i] = w[(size_t)o * 2 * C + C + c] - a;
    }
}

// ---------------- gather + reduce + BN + lrelu ----------------
__global__ void edge_reduce(const float* __restrict__ yz, const int* __restrict__ idx,
                            const float* __restrict__ gg, const float* __restrict__ bb,
                            const float* __restrict__ rm, const float* __restrict__ rv,
                            float* __restrict__ xout, float* __restrict__ outT, int O) {
    const int bn = blockIdx.x;
    const int b = bn >> 11, n = bn & 2047;
    const int o = threadIdx.x;
    __shared__ int sj[KNB];
    if (o < KNB) sj[o] = idx[(size_t)bn * KNB + o];
    __syncthreads();
    const double scale = (double)gg[o] / sqrt((double)rv[o] + 1e-5);
    const int twoO = 2 * O;
    const float z = yz[(size_t)bn * twoO + O + o];
    const int browbase = b << 11;
    float red;
    if (scale >= 0.0) {
        red = -INFINITY;
#pragma unroll
        for (int j = 0; j < KNB; ++j)
            red = fmaxf(red, yz[(size_t)(browbase + sj[j]) * twoO + o]);
    } else {
        red = INFINITY;
#pragma unroll
        for (int j = 0; j < KNB; ++j)
            red = fminf(red, yz[(size_t)(browbase + sj[j]) * twoO + o]);
    }
    double h = (((double)red + (double)z) - (double)rm[o]) * scale + (double)bb[o];
    float hf = (float)h;
    float r = hf >= 0.f ? hf : 0.2f * hf;
    xout[(size_t)bn * O + o] = r;
    if (outT) outT[((size_t)b * O + o) * NPTS + n] = r;
}

// ---------------- global max (two pass) ----------------
__global__ void gmax_partial(const float* __restrict__ x1, const float* __restrict__ x2,
                             const float* __restrict__ x3, const float* __restrict__ x4,
                             float* __restrict__ part) {
    const int b = blockIdx.x, chunk = blockIdx.y;
    const int c = threadIdx.x;  // 0..511
    const float* src; int O, off;
    if (c < 64)       { src = x1; O = 64;  off = c; }
    else if (c < 128) { src = x2; O = 64;  off = c - 64; }
    else if (c < 256) { src = x3; O = 128; off = c - 128; }
    else              { src = x4; O = 256; off = c - 256; }
    float m = -INFINITY;
    const int nbeg = chunk * 128;
    const float* p = src + ((size_t)b * NPTS + nbeg) * O + off;
    for (int n = 0; n < 128; ++n) m = fmaxf(m, p[(size_t)n * O]);
    part[((size_t)b * 16 + chunk) * 512 + c] = m;
}

__global__ void gmax_final(const float* __restrict__ part, float* __restrict__ gmax) {
    const int b = blockIdx.x, c = threadIdx.x;
    float m = -INFINITY;
    for (int ch = 0; ch < 16; ++ch)
        m = fmaxf(m, part[((size_t)b * 16 + ch) * 512 + c]);
    gmax[(size_t)b * 512 + c] = m;
}

// ---------------- final FC + BN + lrelu (fp64 accumulate) ----------------
__global__ void final_fc(const float* __restrict__ gmax, const float* __restrict__ lw,
                         const float* __restrict__ lb, const float* __restrict__ g5,
                         const float* __restrict__ b5, const float* __restrict__ rm5,
                         const float* __restrict__ rv5, float* __restrict__ out) {
    const int b = blockIdx.y;
    const int o = blockIdx.x * 256 + threadIdx.x;
    __shared__ float sg[512];
    for (int i = threadIdx.x; i < 512; i += 256) sg[i] = gmax[(size_t)b * 512 + i];
    __syncthreads();
    const float* wrow = lw + (size_t)o * 512;
    double acc = 0.0;
#pragma unroll 8
    for (int c = 0; c < 512; ++c) acc += (double)sg[c] * (double)wrow[c];
    acc += (double)lb[o];
    const double scale = (double)g5[o] / sqrt((double)rv5[o] + 1e-5);
    double h = (acc - (double)rm5[o]) * scale + (double)b5[o];
    float hf = (float)h;
    out[(size_t)b * 1024 + o] = hf >= 0.f ? hf : 0.2f * hf;
}

// ---------------- launch ----------------
extern "C" void kernel_launch(void* const* d_in, const int* in_sizes, int n_in,
                              void* d_out, int out_size) {
    const float* x    = (const float*)d_in[0];
    const float* w1   = (const float*)d_in[1];
    const float* g1   = (const float*)d_in[2];
    const float* b1   = (const float*)d_in[3];
    const float* rm1  = (const float*)d_in[4];
    const float* rv1  = (const float*)d_in[5];
    const float* w2   = (const float*)d_in[6];
    const float* g2   = (const float*)d_in[7];
    const float* b2   = (const float*)d_in[8];
    const float* rm2  = (const float*)d_in[9];
    const float* rv2  = (const float*)d_in[10];
    const float* w3   = (const float*)d_in[11];
    const float* g3   = (const float*)d_in[12];
    const float* b3   = (const float*)d_in[13];
    const float* rm3  = (const float*)d_in[14];
    const float* rv3  = (const float*)d_in[15];
    const float* w4   = (const float*)d_in[16];
    const float* g4   = (const float*)d_in[17];
    const float* b4   = (const float*)d_in[18];
    const float* rm4  = (const float*)d_in[19];
    const float* rv4  = (const float*)d_in[20];
    const float* lw   = (const float*)d_in[21];
    const float* lb   = (const float*)d_in[22];
    const float* g5   = (const float*)d_in[23];
    const float* b5   = (const float*)d_in[24];
    const float* rm5  = (const float*)d_in[25];
    const float* rv5  = (const float*)d_in[26];

    float *x1, *x2, *x3, *x4, *yz, *wp, *part, *gmax, *dist, *nrmf;
    int *idx, *cand;
    double* nrm;
    cudaGetSymbolAddress((void**)&x1, d_x1);
    cudaGetSymbolAddress((void**)&x2, d_x2);
    cudaGetSymbolAddress((void**)&x3, d_x3);
    cudaGetSymbolAddress((void**)&x4, d_x4);
    cudaGetSymbolAddress((void**)&yz, d_yz);
    cudaGetSymbolAddress((void**)&dist, d_dist);
    cudaGetSymbolAddress((void**)&idx, d_idxbuf);
    cudaGetSymbolAddress((void**)&cand, d_cand);
    cudaGetSymbolAddress((void**)&nrm, d_norm);
    cudaGetSymbolAddress((void**)&nrmf, d_normf);
    cudaGetSymbolAddress((void**)&wp, d_wp);
    cudaGetSymbolAddress((void**)&part, d_part);
    cudaGetSymbolAddress((void**)&gmax, d_gmax);

    float* out = (float*)d_out;
    float* x4T = out + B_ * 1024;

    const dim3 dist_grid(NPTS / 128, NPTS / 128, B_);
    const int nrm_blocks = (MTOT * 32 + 255) / 256;
    const int sel_blocks = MTOT / 4;
    const int rr_blocks = MTOT / 8;

    // layer 1: C=5 -> O=64
    compute_norms<5><<<nrm_blocks, 256>>>(x, nrm, nrmf);
    prep_w<<<(64 * 5 + 255) / 256, 256>>>(w1, wp, 64, 5);
    gemm128<5, false><<<dim3(128 / 128, MTOT / 128, 1), 256>>>(x, wp, nullptr, yz, 128);
    gemm128<5, true><<<dist_grid, 256>>>(x, nullptr, nrmf, dist, NPTS);
    select16<<<sel_blocks, 128>>>(dist, cand);
    rerank<5><<<rr_blocks, 256>>>(x, nrm, cand, idx);
    edge_reduce<<<MTOT, 64>>>(yz, idx, g1, b1, rm1, rv1, x1, nullptr, 64);

    // layer 2: C=64 -> O=64
    compute_norms<64><<<nrm_blocks, 256>>>(x1, nrm, nrmf);
    prep_w<<<(64 * 64 + 255) / 256, 256>>>(w2, wp, 64, 64);
    gemm128<64, false><<<dim3(128 / 128, MTOT / 128, 1), 256>>>(x1, wp, nullptr, yz, 128);
    gemm128<64, true><<<dist_grid, 256>>>(x1, nullptr, nrmf, dist, NPTS);
    select16<<<sel_blocks, 128>>>(dist, cand);
    rerank<64><<<rr_blocks, 256>>>(x1, nrm, cand, idx);
    edge_reduce<<<MTOT, 64>>>(yz, idx, g2, b2, rm2, rv2, x2, nullptr, 64);

    // layer 3: C=64 -> O=128
    compute_norms<64><<<nrm_blocks, 256>>>(x2, nrm, nrmf);
    prep_w<<<(128 * 64 + 255) / 256, 256>>>(w3, wp, 128, 64);
    gemm128<64, false><<<dim3(256 / 128, MTOT / 128, 1), 256>>>(x2, wp, nullptr, yz, 256);
    gemm128<64, true><<<dist_grid, 256>>>(x2, nullptr, nrmf, dist, NPTS);
    select16<<<sel_blocks, 128>>>(dist, cand);
    rerank<64><<<rr_blocks, 256>>>(x2, nrm, cand, idx);
    edge_reduce<<<MTOT, 128>>>(yz, idx, g3, b3, rm3, rv3, x3, nullptr, 128);

    // layer 4: C=128 -> O=256 (also writes transposed output)
    compute_norms<128><<<nrm_blocks, 256>>>(x3, nrm, nrmf);
    prep_w<<<(256 * 128 + 255) / 256, 256>>>(w4, wp, 256, 128);
    gemm128<128, false><<<dim3(512 / 128, MTOT / 128, 1), 256>>>(x3, wp, nullptr, yz, 512);
    gemm128<128, true><<<dist_grid, 256>>>(x3, nullptr, nrmf, dist, NPTS);
    select16<<<sel_blocks, 128>>>(dist, cand);
    rerank<128><<<rr_blocks, 256>>>(x3, nrm, cand, idx);
    edge_reduce<<<MTOT, 256>>>(yz, idx, g4, b4, rm4, rv4, x4, x4T, 256);

    // global max + final FC
    gmax_partial<<<dim3(B_, 16), 512>>>(x1, x2, x3, x4, part);
    gmax_final<<<B_, 512>>>(part, gmax);
    final_fc<<<dim3(4, B_), 256>>>(gmax, lw, lb, g5, b5, rm5, rv5, out);
}